// round 2
// baseline (speedup 1.0000x reference)
#include <cuda_runtime.h>
#include <stdint.h>

#define NN 100000
#define NE 800000

// ---------------- scratch (device globals; no allocation allowed) ----------------
__device__ __align__(16) int    g_deg[NN];
__device__ __align__(16) int    g_cursor[NN];
__device__ __align__(16) float  g_dinv[NN];
__device__ __align__(16) int    g_ptr[NN + 1];
__device__ __align__(16) int    g_src[NE];
__device__ __align__(16) float  g_w[NE];
__device__ __align__(16) float  g_bufA[(size_t)NN * 384];
__device__ __align__(16) float  g_bufB[(size_t)NN * 384];
__device__ __align__(16) float  g_tmpP[(size_t)NN * 128];
__device__ __align__(16) float  g_tmpQ[(size_t)NN * 128];
__device__ double g_sums[768];

// ---------------- graph preprocessing ----------------
__global__ void k_zero_setup() {
    int i = blockIdx.x * blockDim.x + threadIdx.x;
    if (i < NN) { g_deg[i] = 0; g_cursor[i] = 0; }
}

__global__ void k_hist(const int* __restrict__ col) {
    int i = blockIdx.x * blockDim.x + threadIdx.x;
    if (i < NE) atomicAdd(&g_deg[col[i]], 1);
}

__global__ void k_dinv() {
    int i = blockIdx.x * blockDim.x + threadIdx.x;
    if (i < NN) {
        int d = g_deg[i];
        g_dinv[i] = d > 0 ? rsqrtf((float)d) : 0.0f;
    }
}

// exclusive scan of g_deg -> g_ptr, single block, 1024 threads
__global__ void k_scan() {
    __shared__ int sm[1024];
    __shared__ int carry;
    int t = threadIdx.x;
    if (t == 0) carry = 0;
    __syncthreads();
    for (int base = 0; base < NN; base += 1024) {
        int i = base + t;
        int v = (i < NN) ? g_deg[i] : 0;
        sm[t] = v;
        __syncthreads();
        for (int off = 1; off < 1024; off <<= 1) {
            int add = (t >= off) ? sm[t - off] : 0;
            __syncthreads();
            sm[t] += add;
            __syncthreads();
        }
        if (i < NN) g_ptr[i] = carry + sm[t] - v;  // exclusive
        __syncthreads();
        if (t == 0) carry += sm[1023];
        __syncthreads();
    }
    if (t == 0) g_ptr[NN] = carry;
}

__global__ void k_fill(const int* __restrict__ row, const int* __restrict__ col) {
    int i = blockIdx.x * blockDim.x + threadIdx.x;
    if (i >= NE) return;
    int r = row[i], c = col[i];
    int p = g_ptr[c] + atomicAdd(&g_cursor[c], 1);
    g_src[p] = r;
    g_w[p] = g_dinv[r] * g_dinv[c];
}

// ---------------- SPMM: out[d, :] = sum_{e: col=d} w_e * xin[src_e, :] ----------------
// one warp per destination node, 128 features = 32 lanes x float4
__global__ void k_spmm(const float* __restrict__ xin, float* __restrict__ out, int ldo) {
    int warp = (blockIdx.x * blockDim.x + threadIdx.x) >> 5;
    int lane = threadIdx.x & 31;
    if (warp >= NN) return;
    int s = g_ptr[warp], e = g_ptr[warp + 1];
    float4 acc = make_float4(0.f, 0.f, 0.f, 0.f);
    for (int j = s; j < e; j++) {
        int u = __ldg(&g_src[j]);
        float w = __ldg(&g_w[j]);
        float4 v = __ldg(reinterpret_cast<const float4*>(xin + (size_t)u * 128) + lane);
        acc.x = fmaf(w, v.x, acc.x);
        acc.y = fmaf(w, v.y, acc.y);
        acc.z = fmaf(w, v.z, acc.z);
        acc.w = fmaf(w, v.w, acc.w);
    }
    reinterpret_cast<float4*>(out + (size_t)warp * ldo)[lane] = acc;
}

// ---------------- SGEMM: C[M,128] = A[M,K] @ W[K,128] + bias ----------------
// 128x128 tile, BK=8, 256 threads, 8x8 per thread
__global__ void __launch_bounds__(256, 2) k_gemm(
    const float* __restrict__ A, int lda, int M, int K,
    const float* __restrict__ W, const float* __restrict__ bias,
    float* __restrict__ C, int ldc)
{
    __shared__ float As[8][128];
    __shared__ float Bs[8][128];
    const int tid = threadIdx.x;
    const int tx = tid & 15, ty = tid >> 4;
    const int br = blockIdx.x << 7;

    float acc[8][8];
#pragma unroll
    for (int i = 0; i < 8; i++)
#pragma unroll
        for (int j = 0; j < 8; j++) acc[i][j] = 0.f;

    const int arow = tid >> 1;
    const int acol = (tid & 1) << 2;
    const int brow = tid >> 5;
    const int bcol = (tid & 31) << 2;
    const bool aval = (br + arow) < M;
    const float* Ap = A + (size_t)(br + arow) * lda + acol;
    const float* Wp = W + (size_t)brow * 128 + bcol;

    for (int k0 = 0; k0 < K; k0 += 8) {
        float4 av = aval ? *reinterpret_cast<const float4*>(Ap + k0)
                         : make_float4(0.f, 0.f, 0.f, 0.f);
        float4 bv = *reinterpret_cast<const float4*>(Wp + (size_t)k0 * 128);
        __syncthreads();
        As[acol + 0][arow] = av.x;
        As[acol + 1][arow] = av.y;
        As[acol + 2][arow] = av.z;
        As[acol + 3][arow] = av.w;
        *reinterpret_cast<float4*>(&Bs[brow][bcol]) = bv;
        __syncthreads();
#pragma unroll
        for (int k = 0; k < 8; k++) {
            float a[8], b[8];
            *reinterpret_cast<float4*>(&a[0]) = *reinterpret_cast<const float4*>(&As[k][(ty << 2)]);
            *reinterpret_cast<float4*>(&a[4]) = *reinterpret_cast<const float4*>(&As[k][64 + (ty << 2)]);
            *reinterpret_cast<float4*>(&b[0]) = *reinterpret_cast<const float4*>(&Bs[k][(tx << 2)]);
            *reinterpret_cast<float4*>(&b[4]) = *reinterpret_cast<const float4*>(&Bs[k][64 + (tx << 2)]);
#pragma unroll
            for (int i = 0; i < 8; i++)
#pragma unroll
                for (int j = 0; j < 8; j++)
                    acc[i][j] = fmaf(a[i], b[j], acc[i][j]);
        }
    }

#pragma unroll
    for (int i = 0; i < 8; i++) {
        int r = br + ((i < 4) ? (ty << 2) + i : 64 + (ty << 2) + (i - 4));
        if (r >= M) continue;
#pragma unroll
        for (int h = 0; h < 2; h++) {
            int cb = (h ? 64 : 0) + (tx << 2);
            float4 o;
            o.x = acc[i][h * 4 + 0] + bias[cb + 0];
            o.y = acc[i][h * 4 + 1] + bias[cb + 1];
            o.z = acc[i][h * 4 + 2] + bias[cb + 2];
            o.w = acc[i][h * 4 + 3] + bias[cb + 3];
            *reinterpret_cast<float4*>(C + (size_t)r * ldc + cb) = o;
        }
    }
}

// ---------------- BatchNorm + ReLU over [NN, 384] ----------------
__global__ void k_zero_sums() {
    int i = threadIdx.x;
    if (i < 768) g_sums[i] = 0.0;
}

__global__ void k_bnstats(const float* __restrict__ h) {
    int c = threadIdx.x;  // 384 threads
    float s = 0.f, s2 = 0.f;
    for (int r = blockIdx.x; r < NN; r += gridDim.x) {
        float v = h[(size_t)r * 384 + c];
        s += v;
        s2 = fmaf(v, v, s2);
    }
    atomicAdd(&g_sums[c], (double)s);
    atomicAdd(&g_sums[384 + c], (double)s2);
}

__global__ void k_bnapply(float* __restrict__ h,
                          const float* __restrict__ gamma,
                          const float* __restrict__ beta) {
    __shared__ float sc[384], sh[384];
    int c = threadIdx.x;  // 384 threads
    double inv_n = 1.0 / (double)NN;
    double mu = g_sums[c] * inv_n;
    double var = g_sums[384 + c] * inv_n - mu * mu;
    float inv = rsqrtf(fmaxf((float)var, 0.f) + 1e-5f);
    float gg = gamma[c];
    sc[c] = inv * gg;
    sh[c] = beta[c] - (float)mu * inv * gg;
    __syncthreads();
    for (int r = blockIdx.x; r < NN; r += gridDim.x) {
        size_t idx = (size_t)r * 384 + c;
        h[idx] = fmaxf(fmaf(h[idx], sc[c], sh[c]), 0.f);
    }
}

// ---------------- host orchestration ----------------
static void run_layer(const float* X, int Kin, const float* Wl, const float* bl,
                      float* Hout, float* tmpP, float* tmpQ) {
    dim3 gg((NN + 127) / 128);
    const size_t wstep = (size_t)Kin * 128;
    // hop 0 -> cols [0,128)
    k_gemm<<<gg, 256>>>(X, Kin, NN, Kin, Wl, bl, Hout, 384);
    // hop 1 -> cols [128,256)
    k_gemm<<<gg, 256>>>(X, Kin, NN, Kin, Wl + wstep, bl + 128, tmpP, 128);
    k_spmm<<<(NN + 7) / 8, 256>>>(tmpP, Hout + 128, 384);
    // hop 2 -> cols [256,384)
    k_gemm<<<gg, 256>>>(X, Kin, NN, Kin, Wl + 2 * wstep, bl + 256, tmpP, 128);
    k_spmm<<<(NN + 7) / 8, 256>>>(tmpP, tmpQ, 128);
    k_spmm<<<(NN + 7) / 8, 256>>>(tmpQ, Hout + 256, 384);
}

extern "C" void kernel_launch(void* const* d_in, const int* in_sizes, int n_in,
                              void* d_out, int out_size) {
    const float* x  = (const float*)d_in[0];
    const int*   ei = (const int*)d_in[1];
    const float* W0 = (const float*)d_in[2];
    const float* b0 = (const float*)d_in[3];
    const float* W1 = (const float*)d_in[4];
    const float* b1 = (const float*)d_in[5];
    const float* W2 = (const float*)d_in[6];
    const float* b2 = (const float*)d_in[7];
    const float* gm = (const float*)d_in[8];
    const float* bt = (const float*)d_in[9];
    float* out = (float*)d_out;

    float *bufA, *bufB, *tmpP, *tmpQ;
    cudaGetSymbolAddress((void**)&bufA, g_bufA);
    cudaGetSymbolAddress((void**)&bufB, g_bufB);
    cudaGetSymbolAddress((void**)&tmpP, g_tmpP);
    cudaGetSymbolAddress((void**)&tmpQ, g_tmpQ);

    const int* row = ei;
    const int* col = ei + NE;

    // graph preprocessing: degree, norm, CSR by destination
    k_zero_setup<<<(NN + 255) / 256, 256>>>();
    k_hist<<<(NE + 255) / 256, 256>>>(col);
    k_dinv<<<(NN + 255) / 256, 256>>>();
    k_scan<<<1, 1024>>>();
    k_fill<<<(NE + 255) / 256, 256>>>(row, col);

    // layer 0 (Kin = 128, input = x)
    run_layer(x, 128, W0, b0, bufA, tmpP, tmpQ);
    k_zero_sums<<<1, 768>>>();
    k_bnstats<<<512, 384>>>(bufA);
    k_bnapply<<<1024, 384>>>(bufA, gm, bt);

    // layer 1 (Kin = 384)
    run_layer(bufA, 384, W1, b1, bufB, tmpP, tmpQ);
    k_zero_sums<<<1, 768>>>();
    k_bnstats<<<512, 384>>>(bufB);
    k_bnapply<<<1024, 384>>>(bufB, gm + 384, bt + 384);

    // layer 2 (Kin = 384) -> output
    run_layer(bufB, 384, W2, b2, out, tmpP, tmpQ);
}

// round 3
// speedup vs baseline: 1.8411x; 1.8411x over previous
#include <cuda_runtime.h>
#include <stdint.h>

#define NN 100000
#define NE 800000

// ---------------- scratch (device globals; no allocation allowed) ----------------
__device__ __align__(16) int    g_deg[NN];
__device__ __align__(16) int    g_cursor[NN];
__device__ __align__(16) float  g_dinv[NN];
__device__ __align__(16) int    g_ptr[NN + 1];
__device__ __align__(16) int    g_src[NE];
__device__ __align__(16) float  g_w[NE];
__device__ __align__(16) float  g_bufA[(size_t)NN * 384];
__device__ __align__(16) float  g_bufB[(size_t)NN * 384];
__device__ __align__(16) float  g_tmpP[(size_t)NN * 128];
__device__ __align__(16) float  g_tmpQ[(size_t)NN * 128];
__device__ double g_sums[768];
__device__ int g_bsum[128];
__device__ int g_boff[128];

// ---------------- graph preprocessing ----------------
__global__ void k_zero_setup() {
    int i = blockIdx.x * blockDim.x + threadIdx.x;
    if (i < NN) { g_deg[i] = 0; g_cursor[i] = 0; }
}

__global__ void k_hist(const int* __restrict__ col) {
    int i = blockIdx.x * blockDim.x + threadIdx.x;
    if (i < NE) atomicAdd(&g_deg[col[i]], 1);
}

__global__ void k_dinv() {
    int i = blockIdx.x * blockDim.x + threadIdx.x;
    if (i < NN) {
        int d = g_deg[i];
        g_dinv[i] = d > 0 ? rsqrtf((float)d) : 0.0f;
    }
}

// multi-block scan: per-block scan + block sums
__global__ void k_scan1() {
    __shared__ int sm[1024];
    int b = blockIdx.x, t = threadIdx.x;
    int i = b * 1024 + t;
    int v = (i < NN) ? g_deg[i] : 0;
    sm[t] = v;
    __syncthreads();
    for (int off = 1; off < 1024; off <<= 1) {
        int add = (t >= off) ? sm[t - off] : 0;
        __syncthreads();
        sm[t] += add;
        __syncthreads();
    }
    if (i < NN) g_ptr[i] = sm[t] - v;  // exclusive within block
    if (t == 1023) g_bsum[b] = sm[1023];
}

__global__ void k_scan2() {
    __shared__ int sm[128];
    int t = threadIdx.x;
    const int nb = (NN + 1023) >> 10;  // 98
    int v = (t < nb) ? g_bsum[t] : 0;
    sm[t] = v;
    __syncthreads();
    for (int off = 1; off < 128; off <<= 1) {
        int add = (t >= off) ? sm[t - off] : 0;
        __syncthreads();
        sm[t] += add;
        __syncthreads();
    }
    if (t < nb) g_boff[t] = sm[t] - v;
    if (t == 0) g_ptr[NN] = NE;
}

__global__ void k_scan3() {
    int i = blockIdx.x * blockDim.x + threadIdx.x;
    if (i < NN) g_ptr[i] += g_boff[i >> 10];
}

__global__ void k_fill(const int* __restrict__ row, const int* __restrict__ col) {
    int i = blockIdx.x * blockDim.x + threadIdx.x;
    if (i >= NE) return;
    int r = row[i], c = col[i];
    int p = g_ptr[c] + atomicAdd(&g_cursor[c], 1);
    g_src[p] = r;
    g_w[p] = g_dinv[r] * g_dinv[c];
}

// ---------------- SPMM: out[d, :] = sum_{e: col=d} w_e * xin[src_e, :] ----------------
__global__ void k_spmm(const float* __restrict__ xin, float* __restrict__ out, int ldo) {
    int warp = (blockIdx.x * blockDim.x + threadIdx.x) >> 5;
    int lane = threadIdx.x & 31;
    if (warp >= NN) return;
    int s = g_ptr[warp], e = g_ptr[warp + 1];
    float4 acc = make_float4(0.f, 0.f, 0.f, 0.f);
    for (int j = s; j < e; j++) {
        int u = __ldg(&g_src[j]);
        float w = __ldg(&g_w[j]);
        float4 v = __ldg(reinterpret_cast<const float4*>(xin + (size_t)u * 128) + lane);
        acc.x = fmaf(w, v.x, acc.x);
        acc.y = fmaf(w, v.y, acc.y);
        acc.z = fmaf(w, v.z, acc.z);
        acc.w = fmaf(w, v.w, acc.w);
    }
    reinterpret_cast<float4*>(out + (size_t)warp * ldo)[lane] = acc;
}

// ---------------- TF32 tensor-core GEMM: C[M,128] = A[M,K] @ W[K,128] + bias --------
__device__ __forceinline__ uint32_t f2tf32(float x) {
    uint32_t r;
    asm("cvt.rna.tf32.f32 %0, %1;" : "=r"(r) : "f"(x));
    return r;
}

__device__ __forceinline__ void mma_tf32(float* d, const uint32_t* a, const uint32_t* b) {
    asm volatile(
        "mma.sync.aligned.m16n8k8.row.col.f32.tf32.tf32.f32 "
        "{%0,%1,%2,%3}, {%4,%5,%6,%7}, {%8,%9}, {%0,%1,%2,%3};\n"
        : "+f"(d[0]), "+f"(d[1]), "+f"(d[2]), "+f"(d[3])
        : "r"(a[0]), "r"(a[1]), "r"(a[2]), "r"(a[3]),
          "r"(b[0]), "r"(b[1]));
}

#define APITCH 20   // As row pitch (floats) -> conflict-free A frags
#define BPITCH 136  // Bs row pitch (floats) -> conflict-free B frags

__device__ __forceinline__ void gemm_ldg(
    const float* __restrict__ A, int lda, int M, int row0,
    const float* __restrict__ W, int kt, int tid,
    float4* regA, float4* regB)
{
    const int kb = kt * 16;
#pragma unroll
    for (int j = 0; j < 4; j++) {
        int m = (tid >> 2) + j * 32;
        int c4 = (tid & 3) * 4;
        if (row0 + m < M)
            regA[j] = *reinterpret_cast<const float4*>(A + (size_t)(row0 + m) * lda + kb + c4);
        else
            regA[j] = make_float4(0.f, 0.f, 0.f, 0.f);
        int kl = (tid >> 5) + j * 4;
        int n4 = (tid & 31) * 4;
        regB[j] = *reinterpret_cast<const float4*>(W + (size_t)(kb + kl) * 128 + n4);
    }
}

__device__ __forceinline__ void gemm_sts(
    uint32_t* __restrict__ As, uint32_t* __restrict__ Bs, int tid,
    const float4* regA, const float4* regB)
{
#pragma unroll
    for (int j = 0; j < 4; j++) {
        int m = (tid >> 2) + j * 32;
        int c4 = (tid & 3) * 4;
        uint32_t* p = As + m * APITCH + c4;
        p[0] = f2tf32(regA[j].x);
        p[1] = f2tf32(regA[j].y);
        p[2] = f2tf32(regA[j].z);
        p[3] = f2tf32(regA[j].w);
        int kl = (tid >> 5) + j * 4;
        int n4 = (tid & 31) * 4;
        uint32_t* q = Bs + kl * BPITCH + n4;
        q[0] = f2tf32(regB[j].x);
        q[1] = f2tf32(regB[j].y);
        q[2] = f2tf32(regB[j].z);
        q[3] = f2tf32(regB[j].w);
    }
}

__global__ void __launch_bounds__(128, 2) k_gemm_tf32(
    const float* __restrict__ A, int lda, int M, int K,
    const float* __restrict__ W, const float* __restrict__ bias,
    float* __restrict__ C, int ldc)
{
    __shared__ uint32_t As[2][128 * APITCH];
    __shared__ uint32_t Bs[2][16 * BPITCH];

    const int tid = threadIdx.x;
    const int wid = tid >> 5, lane = tid & 31;
    const int g = lane >> 2, t = lane & 3;
    const int wm = (wid >> 1) * 64, wn = (wid & 1) * 64;
    const int row0 = blockIdx.x * 128;

    float acc[4][8][4];
#pragma unroll
    for (int im = 0; im < 4; im++)
#pragma unroll
        for (int in = 0; in < 8; in++)
#pragma unroll
            for (int q = 0; q < 4; q++) acc[im][in][q] = 0.f;

    const int NT = K >> 4;
    float4 regA[4], regB[4];

    gemm_ldg(A, lda, M, row0, W, 0, tid, regA, regB);
    gemm_sts(As[0], Bs[0], tid, regA, regB);
    __syncthreads();

    for (int kt = 0; kt < NT; kt++) {
        const int buf = kt & 1;
        if (kt + 1 < NT) gemm_ldg(A, lda, M, row0, W, kt + 1, tid, regA, regB);

        const uint32_t* Ab = As[buf];
        const uint32_t* Bb = Bs[buf];
#pragma unroll
        for (int ks = 0; ks < 16; ks += 8) {
            uint32_t af[4][4], bf[8][2];
#pragma unroll
            for (int im = 0; im < 4; im++) {
                int mb = (wm + im * 16 + g) * APITCH + ks + t;
                af[im][0] = Ab[mb];
                af[im][1] = Ab[mb + 8 * APITCH];
                af[im][2] = Ab[mb + 4];
                af[im][3] = Ab[mb + 8 * APITCH + 4];
            }
#pragma unroll
            for (int in = 0; in < 8; in++) {
                int nb = (ks + t) * BPITCH + wn + in * 8 + g;
                bf[in][0] = Bb[nb];
                bf[in][1] = Bb[nb + 4 * BPITCH];
            }
#pragma unroll
            for (int im = 0; im < 4; im++)
#pragma unroll
                for (int in = 0; in < 8; in++)
                    mma_tf32(acc[im][in], af[im], bf[in]);
        }

        if (kt + 1 < NT) {
            gemm_sts(As[buf ^ 1], Bs[buf ^ 1], tid, regA, regB);
            __syncthreads();
        }
    }

    // epilogue: bias + store
#pragma unroll
    for (int im = 0; im < 4; im++) {
        int r0 = row0 + wm + im * 16 + g;
#pragma unroll
        for (int in = 0; in < 8; in++) {
            int c0 = wn + in * 8 + 2 * t;
            float b0 = __ldg(&bias[c0]), b1 = __ldg(&bias[c0 + 1]);
            if (r0 < M) {
                float2 v = make_float2(acc[im][in][0] + b0, acc[im][in][1] + b1);
                *reinterpret_cast<float2*>(C + (size_t)r0 * ldc + c0) = v;
            }
            if (r0 + 8 < M) {
                float2 v = make_float2(acc[im][in][2] + b0, acc[im][in][3] + b1);
                *reinterpret_cast<float2*>(C + (size_t)(r0 + 8) * ldc + c0) = v;
            }
        }
    }
}

// ---------------- BatchNorm + ReLU over [NN, 384] ----------------
__global__ void k_zero_sums() {
    int i = threadIdx.x;
    if (i < 768) g_sums[i] = 0.0;
}

__global__ void k_bnstats(const float* __restrict__ h) {
    int c = threadIdx.x;  // 384 threads
    float s = 0.f, s2 = 0.f;
    for (int r = blockIdx.x; r < NN; r += gridDim.x) {
        float v = h[(size_t)r * 384 + c];
        s += v;
        s2 = fmaf(v, v, s2);
    }
    atomicAdd(&g_sums[c], (double)s);
    atomicAdd(&g_sums[384 + c], (double)s2);
}

__global__ void k_bnapply(float* __restrict__ h,
                          const float* __restrict__ gamma,
                          const float* __restrict__ beta) {
    __shared__ float sc[384], sh[384];
    int c = threadIdx.x;  // 384 threads
    double inv_n = 1.0 / (double)NN;
    double mu = g_sums[c] * inv_n;
    double var = g_sums[384 + c] * inv_n - mu * mu;
    float inv = rsqrtf(fmaxf((float)var, 0.f) + 1e-5f);
    float gg = gamma[c];
    sc[c] = inv * gg;
    sh[c] = beta[c] - (float)mu * inv * gg;
    __syncthreads();
    for (int r = blockIdx.x; r < NN; r += gridDim.x) {
        size_t idx = (size_t)r * 384 + c;
        h[idx] = fmaxf(fmaf(h[idx], sc[c], sh[c]), 0.f);
    }
}

// ---------------- host orchestration ----------------
static void run_layer(const float* X, int Kin, const float* Wl, const float* bl,
                      float* Hout, float* tmpP, float* tmpQ) {
    dim3 gg((NN + 127) / 128);
    const size_t wstep = (size_t)Kin * 128;
    // hop 0 -> cols [0,128)
    k_gemm_tf32<<<gg, 128>>>(X, Kin, NN, Kin, Wl, bl, Hout, 384);
    // hop 1 -> cols [128,256)
    k_gemm_tf32<<<gg, 128>>>(X, Kin, NN, Kin, Wl + wstep, bl + 128, tmpP, 128);
    k_spmm<<<(NN + 7) / 8, 256>>>(tmpP, Hout + 128, 384);
    // hop 2 -> cols [256,384)
    k_gemm_tf32<<<gg, 128>>>(X, Kin, NN, Kin, Wl + 2 * wstep, bl + 256, tmpP, 128);
    k_spmm<<<(NN + 7) / 8, 256>>>(tmpP, tmpQ, 128);
    k_spmm<<<(NN + 7) / 8, 256>>>(tmpQ, Hout + 256, 384);
}

extern "C" void kernel_launch(void* const* d_in, const int* in_sizes, int n_in,
                              void* d_out, int out_size) {
    const float* x  = (const float*)d_in[0];
    const int*   ei = (const int*)d_in[1];
    const float* W0 = (const float*)d_in[2];
    const float* b0 = (const float*)d_in[3];
    const float* W1 = (const float*)d_in[4];
    const float* b1 = (const float*)d_in[5];
    const float* W2 = (const float*)d_in[6];
    const float* b2 = (const float*)d_in[7];
    const float* gm = (const float*)d_in[8];
    const float* bt = (const float*)d_in[9];
    float* out = (float*)d_out;

    float *bufA, *bufB, *tmpP, *tmpQ;
    cudaGetSymbolAddress((void**)&bufA, g_bufA);
    cudaGetSymbolAddress((void**)&bufB, g_bufB);
    cudaGetSymbolAddress((void**)&tmpP, g_tmpP);
    cudaGetSymbolAddress((void**)&tmpQ, g_tmpQ);

    const int* row = ei;
    const int* col = ei + NE;

    // graph preprocessing: degree, norm, CSR by destination
    k_zero_setup<<<(NN + 255) / 256, 256>>>();
    k_hist<<<(NE + 255) / 256, 256>>>(col);
    k_dinv<<<(NN + 255) / 256, 256>>>();
    k_scan1<<<(NN + 1023) / 1024, 1024>>>();
    k_scan2<<<1, 128>>>();
    k_scan3<<<(NN + 255) / 256, 256>>>();
    k_fill<<<(NE + 255) / 256, 256>>>(row, col);

    // layer 0 (Kin = 128, input = x)
    run_layer(x, 128, W0, b0, bufA, tmpP, tmpQ);
    k_zero_sums<<<1, 768>>>();
    k_bnstats<<<512, 384>>>(bufA);
    k_bnapply<<<1024, 384>>>(bufA, gm, bt);

    // layer 1 (Kin = 384)
    run_layer(bufA, 384, W1, b1, bufB, tmpP, tmpQ);
    k_zero_sums<<<1, 768>>>();
    k_bnstats<<<512, 384>>>(bufB);
    k_bnapply<<<1024, 384>>>(bufB, gm + 384, bt + 384);

    // layer 2 (Kin = 384) -> output
    run_layer(bufB, 384, W2, b2, out, tmpP, tmpQ);
}

// round 6
// speedup vs baseline: 1.8496x; 1.0046x over previous
#include <cuda_runtime.h>
#include <stdint.h>

#define NN 100000
#define NE 800000

// ---------------- scratch (device globals; no allocation allowed) ----------------
__device__ __align__(16) int    g_deg[NN];
__device__ __align__(16) int    g_cursor[NN];
__device__ __align__(16) float  g_dinv[NN];
__device__ __align__(16) int    g_ptr[NN + 1];
__device__ __align__(16) int    g_src[NE];
__device__ __align__(16) float  g_w[NE];
__device__ __align__(16) float  g_bufA[(size_t)NN * 384];
__device__ __align__(16) float  g_bufB[(size_t)NN * 384];
__device__ __align__(16) float  g_tmpT[(size_t)NN * 256];
__device__ __align__(16) float  g_tmpQ[(size_t)NN * 128];
__device__ __align__(16) float  g_sc[384];
__device__ __align__(16) float  g_sh[384];
__device__ double g_sums[768];
__device__ int g_bsum[128];
__device__ int g_boff[128];

// ---------------- graph preprocessing ----------------
__global__ void k_zero_setup() {
    int i = blockIdx.x * blockDim.x + threadIdx.x;
    if (i < NN) { g_deg[i] = 0; g_cursor[i] = 0; }
}
__global__ void k_hist(const int* __restrict__ col) {
    int i = blockIdx.x * blockDim.x + threadIdx.x;
    if (i < NE) atomicAdd(&g_deg[col[i]], 1);
}
__global__ void k_dinv() {
    int i = blockIdx.x * blockDim.x + threadIdx.x;
    if (i < NN) {
        int d = g_deg[i];
        g_dinv[i] = d > 0 ? rsqrtf((float)d) : 0.0f;
    }
}
__global__ void k_scan1() {
    __shared__ int sm[1024];
    int b = blockIdx.x, t = threadIdx.x;
    int i = b * 1024 + t;
    int v = (i < NN) ? g_deg[i] : 0;
    sm[t] = v;
    __syncthreads();
    for (int off = 1; off < 1024; off <<= 1) {
        int add = (t >= off) ? sm[t - off] : 0;
        __syncthreads();
        sm[t] += add;
        __syncthreads();
    }
    if (i < NN) g_ptr[i] = sm[t] - v;
    if (t == 1023) g_bsum[b] = sm[1023];
}
__global__ void k_scan2() {
    __shared__ int sm[128];
    int t = threadIdx.x;
    const int nb = (NN + 1023) >> 10;
    int v = (t < nb) ? g_bsum[t] : 0;
    sm[t] = v;
    __syncthreads();
    for (int off = 1; off < 128; off <<= 1) {
        int add = (t >= off) ? sm[t - off] : 0;
        __syncthreads();
        sm[t] += add;
        __syncthreads();
    }
    if (t < nb) g_boff[t] = sm[t] - v;
    if (t == 0) g_ptr[NN] = NE;
}
__global__ void k_scan3() {
    int i = blockIdx.x * blockDim.x + threadIdx.x;
    if (i < NN) g_ptr[i] += g_boff[i >> 10];
}
__global__ void k_fill(const int* __restrict__ row, const int* __restrict__ col) {
    int i = blockIdx.x * blockDim.x + threadIdx.x;
    if (i >= NE) return;
    int r = row[i], c = col[i];
    int p = g_ptr[c] + atomicAdd(&g_cursor[c], 1);
    g_src[p] = r;
    g_w[p] = g_dinv[r] * g_dinv[c];
}

// ---------------- SPMM kernels ----------------
__global__ void k_spmm(const float* __restrict__ xin, int ldi,
                       float* __restrict__ out, int ldo) {
    int warp = (blockIdx.x * blockDim.x + threadIdx.x) >> 5;
    int lane = threadIdx.x & 31;
    if (warp >= NN) return;
    int s = g_ptr[warp], e = g_ptr[warp + 1];
    float4 acc = make_float4(0.f, 0.f, 0.f, 0.f);
    for (int j = s; j < e; j++) {
        int u = __ldg(&g_src[j]);
        float w = __ldg(&g_w[j]);
        float4 v = __ldg(reinterpret_cast<const float4*>(xin + (size_t)u * ldi) + lane);
        acc.x = fmaf(w, v.x, acc.x);
        acc.y = fmaf(w, v.y, acc.y);
        acc.z = fmaf(w, v.z, acc.z);
        acc.w = fmaf(w, v.w, acc.w);
    }
    reinterpret_cast<float4*>(out + (size_t)warp * ldo)[lane] = acc;
}

// merged SPMM over T [NN,256]: cols [0,128) -> out1, cols [128,256) -> out2
__global__ void k_spmm256(const float* __restrict__ T,
                          float* __restrict__ out1, int ld1,
                          float* __restrict__ out2, int ld2) {
    int warp = (blockIdx.x * blockDim.x + threadIdx.x) >> 5;
    int lane = threadIdx.x & 31;
    if (warp >= NN) return;
    int s = g_ptr[warp], e = g_ptr[warp + 1];
    float4 a1 = make_float4(0.f, 0.f, 0.f, 0.f);
    float4 a2 = make_float4(0.f, 0.f, 0.f, 0.f);
    for (int j = s; j < e; j++) {
        int u = __ldg(&g_src[j]);
        float w = __ldg(&g_w[j]);
        const float4* rp = reinterpret_cast<const float4*>(T + (size_t)u * 256);
        float4 v1 = __ldg(rp + lane);
        float4 v2 = __ldg(rp + 32 + lane);
        a1.x = fmaf(w, v1.x, a1.x); a1.y = fmaf(w, v1.y, a1.y);
        a1.z = fmaf(w, v1.z, a1.z); a1.w = fmaf(w, v1.w, a1.w);
        a2.x = fmaf(w, v2.x, a2.x); a2.y = fmaf(w, v2.y, a2.y);
        a2.z = fmaf(w, v2.z, a2.z); a2.w = fmaf(w, v2.w, a2.w);
    }
    reinterpret_cast<float4*>(out1 + (size_t)warp * ld1)[lane] = a1;
    reinterpret_cast<float4*>(out2 + (size_t)warp * ld2)[lane] = a2;
}

// ---------------- TF32 tensor-core GEMM with fused BN+ReLU on A ----------------
__device__ __forceinline__ uint32_t f2tf32(float x) {
    uint32_t r;
    asm("cvt.rna.tf32.f32 %0, %1;" : "=r"(r) : "f"(x));
    return r;
}
__device__ __forceinline__ void mma_tf32(float* d, const uint32_t* a, const uint32_t* b) {
    asm volatile(
        "mma.sync.aligned.m16n8k8.row.col.f32.tf32.tf32.f32 "
        "{%0,%1,%2,%3}, {%4,%5,%6,%7}, {%8,%9}, {%0,%1,%2,%3};\n"
        : "+f"(d[0]), "+f"(d[1]), "+f"(d[2]), "+f"(d[3])
        : "r"(a[0]), "r"(a[1]), "r"(a[2]), "r"(a[3]),
          "r"(b[0]), "r"(b[1]));
}

#define APITCH 20
#define BPITCH 136

__device__ __forceinline__ void gemm_ldg(
    const float* __restrict__ A, int lda, int M, int row0,
    const float* __restrict__ W, int kt, int tid,
    const float* __restrict__ bnsc, const float* __restrict__ bnsh,
    float4* regA, float4* regB)
{
    const int kb = kt * 16;
    const int c4 = (tid & 3) * 4;
    float4 scv = make_float4(1.f, 1.f, 1.f, 1.f);
    float4 shv = make_float4(0.f, 0.f, 0.f, 0.f);
    if (bnsc) {
        scv = *reinterpret_cast<const float4*>(bnsc + kb + c4);
        shv = *reinterpret_cast<const float4*>(bnsh + kb + c4);
    }
#pragma unroll
    for (int j = 0; j < 4; j++) {
        int m = (tid >> 2) + j * 32;
        float4 v = make_float4(0.f, 0.f, 0.f, 0.f);
        if (row0 + m < M)
            v = *reinterpret_cast<const float4*>(A + (size_t)(row0 + m) * lda + kb + c4);
        if (bnsc) {
            v.x = fmaxf(fmaf(v.x, scv.x, shv.x), 0.f);
            v.y = fmaxf(fmaf(v.y, scv.y, shv.y), 0.f);
            v.z = fmaxf(fmaf(v.z, scv.z, shv.z), 0.f);
            v.w = fmaxf(fmaf(v.w, scv.w, shv.w), 0.f);
        }
        regA[j] = v;
        int kl = (tid >> 5) + j * 4;
        int n4 = (tid & 31) * 4;
        regB[j] = *reinterpret_cast<const float4*>(W + (size_t)(kb + kl) * 128 + n4);
    }
}

__device__ __forceinline__ void gemm_sts(
    uint32_t* __restrict__ As, uint32_t* __restrict__ Bs, int tid,
    const float4* regA, const float4* regB)
{
#pragma unroll
    for (int j = 0; j < 4; j++) {
        int m = (tid >> 2) + j * 32;
        int c4 = (tid & 3) * 4;
        uint32_t* p = As + m * APITCH + c4;
        p[0] = f2tf32(regA[j].x);
        p[1] = f2tf32(regA[j].y);
        p[2] = f2tf32(regA[j].z);
        p[3] = f2tf32(regA[j].w);
        int kl = (tid >> 5) + j * 4;
        int n4 = (tid & 31) * 4;
        uint32_t* q = Bs + kl * BPITCH + n4;
        q[0] = f2tf32(regB[j].x);
        q[1] = f2tf32(regB[j].y);
        q[2] = f2tf32(regB[j].z);
        q[3] = f2tf32(regB[j].w);
    }
}

__global__ void __launch_bounds__(128, 2) k_gemm_tf32(
    const float* __restrict__ A, int lda, int M, int K,
    const float* __restrict__ W, const float* __restrict__ bias,
    const float* __restrict__ bnsc, const float* __restrict__ bnsh,
    float* __restrict__ C, int ldc)
{
    __shared__ uint32_t As[2][128 * APITCH];
    __shared__ uint32_t Bs[2][16 * BPITCH];

    const int tid = threadIdx.x;
    const int wid = tid >> 5, lane = tid & 31;
    const int g = lane >> 2, t = lane & 3;
    const int wm = (wid >> 1) * 64, wn = (wid & 1) * 64;
    const int row0 = blockIdx.x * 128;

    float acc[4][8][4];
#pragma unroll
    for (int im = 0; im < 4; im++)
#pragma unroll
        for (int in = 0; in < 8; in++)
#pragma unroll
            for (int q = 0; q < 4; q++) acc[im][in][q] = 0.f;

    const int NT = K >> 4;
    float4 regA[4], regB[4];

    gemm_ldg(A, lda, M, row0, W, 0, tid, bnsc, bnsh, regA, regB);
    gemm_sts(As[0], Bs[0], tid, regA, regB);
    __syncthreads();

    for (int kt = 0; kt < NT; kt++) {
        const int buf = kt & 1;
        if (kt + 1 < NT) gemm_ldg(A, lda, M, row0, W, kt + 1, tid, bnsc, bnsh, regA, regB);

        const uint32_t* Ab = As[buf];
        const uint32_t* Bb = Bs[buf];
#pragma unroll
        for (int ks = 0; ks < 16; ks += 8) {
            uint32_t af[4][4], bf[8][2];
#pragma unroll
            for (int im = 0; im < 4; im++) {
                int mb = (wm + im * 16 + g) * APITCH + ks + t;
                af[im][0] = Ab[mb];
                af[im][1] = Ab[mb + 8 * APITCH];
                af[im][2] = Ab[mb + 4];
                af[im][3] = Ab[mb + 8 * APITCH + 4];
            }
#pragma unroll
            for (int in = 0; in < 8; in++) {
                int nb = (ks + t) * BPITCH + wn + in * 8 + g;
                bf[in][0] = Bb[nb];
                bf[in][1] = Bb[nb + 4 * BPITCH];
            }
#pragma unroll
            for (int im = 0; im < 4; im++)
#pragma unroll
                for (int in = 0; in < 8; in++)
                    mma_tf32(acc[im][in], af[im], bf[in]);
        }

        if (kt + 1 < NT) {
            gemm_sts(As[buf ^ 1], Bs[buf ^ 1], tid, regA, regB);
            __syncthreads();
        }
    }

    // epilogue: bias + store
#pragma unroll
    for (int im = 0; im < 4; im++) {
        int r0 = row0 + wm + im * 16 + g;
#pragma unroll
        for (int in = 0; in < 8; in++) {
            int c0 = wn + in * 8 + 2 * t;
            float b0 = __ldg(&bias[c0]), b1 = __ldg(&bias[c0 + 1]);
            if (r0 < M) {
                float2 v = make_float2(acc[im][in][0] + b0, acc[im][in][1] + b1);
                *reinterpret_cast<float2*>(C + (size_t)r0 * ldc + c0) = v;
            }
            if (r0 + 8 < M) {
                float2 v = make_float2(acc[im][in][2] + b0, acc[im][in][3] + b1);
                *reinterpret_cast<float2*>(C + (size_t)(r0 + 8) * ldc + c0) = v;
            }
        }
    }
}

// ---------------- BatchNorm stats + coefficients ----------------
__global__ void k_zero_sums() {
    int i = threadIdx.x;
    if (i < 768) g_sums[i] = 0.0;
}
__global__ void k_bnstats(const float* __restrict__ h) {
    int c = threadIdx.x;  // 384 threads
    float s = 0.f, s2 = 0.f;
    for (int r = blockIdx.x; r < NN; r += gridDim.x) {
        float v = h[(size_t)r * 384 + c];
        s += v;
        s2 = fmaf(v, v, s2);
    }
    atomicAdd(&g_sums[c], (double)s);
    atomicAdd(&g_sums[384 + c], (double)s2);
}
__global__ void k_bncoef(const float* __restrict__ gamma, const float* __restrict__ beta) {
    int c = threadIdx.x;  // 384
    double inv_n = 1.0 / (double)NN;
    double mu = g_sums[c] * inv_n;
    double var = g_sums[384 + c] * inv_n - mu * mu;
    float inv = rsqrtf(fmaxf((float)var, 0.f) + 1e-5f);
    float gg = gamma[c];
    g_sc[c] = inv * gg;
    g_sh[c] = beta[c] - (float)mu * inv * gg;
}

// ---------------- host orchestration ----------------
static void run_layer(const float* X, int Kin, const float* Wl, const float* bl,
                      const float* bnsc, const float* bnsh,
                      float* Hout, float* T, float* tmpQ) {
    dim3 gg((NN + 127) / 128);
    const size_t wstep = (size_t)Kin * 128;
    // hop 0 -> Hout cols [0,128)
    k_gemm_tf32<<<gg, 128>>>(X, Kin, NN, Kin, Wl, bl, bnsc, bnsh, Hout, 384);
    // hop 1 pre-spmm -> T cols [0,128)
    k_gemm_tf32<<<gg, 128>>>(X, Kin, NN, Kin, Wl + wstep, bl + 128, bnsc, bnsh, T, 256);
    // hop 2 pre-spmm -> T cols [128,256)
    k_gemm_tf32<<<gg, 128>>>(X, Kin, NN, Kin, Wl + 2 * wstep, bl + 256, bnsc, bnsh, T + 128, 256);
    // one edge pass for both: hop1 -> Hout+128, hop2 stage1 -> tmpQ
    k_spmm256<<<(NN + 7) / 8, 256>>>(T, Hout + 128, 384, tmpQ, 128);
    // hop2 stage2 -> Hout+256
    k_spmm<<<(NN + 7) / 8, 256>>>(tmpQ, 128, Hout + 256, 384);
}

extern "C" void kernel_launch(void* const* d_in, const int* in_sizes, int n_in,
                              void* d_out, int out_size) {
    const float* x  = (const float*)d_in[0];
    const int*   ei = (const int*)d_in[1];
    const float* W0 = (const float*)d_in[2];
    const float* b0 = (const float*)d_in[3];
    const float* W1 = (const float*)d_in[4];
    const float* b1 = (const float*)d_in[5];
    const float* W2 = (const float*)d_in[6];
    const float* b2 = (const float*)d_in[7];
    const float* gm = (const float*)d_in[8];
    const float* bt = (const float*)d_in[9];
    float* out = (float*)d_out;

    float *bufA, *bufB, *T, *tmpQ, *sc, *sh;
    cudaGetSymbolAddress((void**)&bufA, g_bufA);
    cudaGetSymbolAddress((void**)&bufB, g_bufB);
    cudaGetSymbolAddress((void**)&T, g_tmpT);
    cudaGetSymbolAddress((void**)&tmpQ, g_tmpQ);
    cudaGetSymbolAddress((void**)&sc, g_sc);
    cudaGetSymbolAddress((void**)&sh, g_sh);

    const int* row = ei;
    const int* col = ei + NE;

    // graph preprocessing: degree, norm, CSR by destination
    k_zero_setup<<<(NN + 255) / 256, 256>>>();
    k_hist<<<(NE + 255) / 256, 256>>>(col);
    k_dinv<<<(NN + 255) / 256, 256>>>();
    k_scan1<<<(NN + 1023) / 1024, 1024>>>();
    k_scan2<<<1, 128>>>();
    k_scan3<<<(NN + 255) / 256, 256>>>();
    k_fill<<<(NE + 255) / 256, 256>>>(row, col);

    // layer 0 (no BN on input)
    run_layer(x, 128, W0, b0, nullptr, nullptr, bufA, T, tmpQ);
    k_zero_sums<<<1, 768>>>();
    k_bnstats<<<512, 384>>>(bufA);
    k_bncoef<<<1, 384>>>(gm, bt);

    // layer 1 (BN0+ReLU fused into A-load)
    run_layer(bufA, 384, W1, b1, sc, sh, bufB, T, tmpQ);
    k_zero_sums<<<1, 768>>>();
    k_bnstats<<<512, 384>>>(bufB);
    k_bncoef<<<1, 384>>>(gm + 384, bt + 384);

    // layer 2 (BN1+ReLU fused into A-load) -> output
    run_layer(bufB, 384, W2, b2, sc, sh, out, T, tmpQ);
}

// round 7
// speedup vs baseline: 2.1305x; 1.1519x over previous
#include <cuda_runtime.h>
#include <stdint.h>

#define NN 100000
#define NE 800000

// ---------------- scratch (device globals; no allocation allowed) ----------------
__device__ __align__(16) int    g_deg[NN];
__device__ __align__(16) int    g_cursor[NN];
__device__ __align__(16) float  g_dinv[NN];
__device__ __align__(16) int    g_ptr[NN + 1];
__device__ __align__(16) int    g_src[NE];
__device__ __align__(16) float  g_w[NE];
__device__ __align__(16) float  g_bufA[(size_t)NN * 384];
__device__ __align__(16) float  g_bufB[(size_t)NN * 384];
__device__ __align__(16) float  g_tmpT[(size_t)NN * 256];
__device__ __align__(16) float  g_tmpQ[(size_t)NN * 128];
__device__ __align__(16) float  g_sc[384];
__device__ __align__(16) float  g_sh[384];
__device__ double g_sums[768];
__device__ int g_bsum[128];
__device__ int g_boff[128];

// ---------------- graph preprocessing ----------------
__global__ void k_zero_setup() {
    int i = blockIdx.x * blockDim.x + threadIdx.x;
    if (i < NN) { g_deg[i] = 0; g_cursor[i] = 0; }
}
__global__ void k_hist(const int* __restrict__ col) {
    int i = blockIdx.x * blockDim.x + threadIdx.x;
    if (i < NE) atomicAdd(&g_deg[col[i]], 1);
}
__global__ void k_dinv() {
    int i = blockIdx.x * blockDim.x + threadIdx.x;
    if (i < NN) {
        int d = g_deg[i];
        g_dinv[i] = d > 0 ? rsqrtf((float)d) : 0.0f;
    }
}
__global__ void k_scan1() {
    __shared__ int sm[1024];
    int b = blockIdx.x, t = threadIdx.x;
    int i = b * 1024 + t;
    int v = (i < NN) ? g_deg[i] : 0;
    sm[t] = v;
    __syncthreads();
    for (int off = 1; off < 1024; off <<= 1) {
        int add = (t >= off) ? sm[t - off] : 0;
        __syncthreads();
        sm[t] += add;
        __syncthreads();
    }
    if (i < NN) g_ptr[i] = sm[t] - v;
    if (t == 1023) g_bsum[b] = sm[1023];
}
__global__ void k_scan2() {
    __shared__ int sm[128];
    int t = threadIdx.x;
    const int nb = (NN + 1023) >> 10;
    int v = (t < nb) ? g_bsum[t] : 0;
    sm[t] = v;
    __syncthreads();
    for (int off = 1; off < 128; off <<= 1) {
        int add = (t >= off) ? sm[t - off] : 0;
        __syncthreads();
        sm[t] += add;
        __syncthreads();
    }
    if (t < nb) g_boff[t] = sm[t] - v;
    if (t == 0) g_ptr[NN] = NE;
}
__global__ void k_scan3() {
    int i = blockIdx.x * blockDim.x + threadIdx.x;
    if (i < NN) g_ptr[i] += g_boff[i >> 10];
}
__global__ void k_fill(const int* __restrict__ row, const int* __restrict__ col) {
    int i = blockIdx.x * blockDim.x + threadIdx.x;
    if (i >= NE) return;
    int r = row[i], c = col[i];
    int p = g_ptr[c] + atomicAdd(&g_cursor[c], 1);
    g_src[p] = r;
    g_w[p] = g_dinv[r] * g_dinv[c];
}

// ---------------- SPMM kernels (8 nodes per warp, fused BN stats) ----------------
// merged SPMM over T [NN,256]: cols [0,128) -> out1 (h cols 128:256, stats),
//                              cols [128,256) -> out2 (intermediate, no stats)
__global__ void __launch_bounds__(256) k_spmm256(
    const float* __restrict__ T,
    float* __restrict__ out1, int ld1,
    float* __restrict__ out2, int ld2, int do_stats)
{
    __shared__ float ssum[128], ssq[128];
    const int tid = threadIdx.x;
    if (tid < 128) { ssum[tid] = 0.f; ssq[tid] = 0.f; }
    __syncthreads();
    const int lane = tid & 31, wp = tid >> 5;
    const int base = blockIdx.x * 64 + wp * 8;
    float ls[4] = {0.f, 0.f, 0.f, 0.f};
    float lq[4] = {0.f, 0.f, 0.f, 0.f};
    for (int nn = 0; nn < 8; nn++) {
        int node = base + nn;
        if (node >= NN) break;
        int s = g_ptr[node], e = g_ptr[node + 1];
        float4 a1 = make_float4(0.f, 0.f, 0.f, 0.f);
        float4 a2 = make_float4(0.f, 0.f, 0.f, 0.f);
        for (int j = s; j < e; j++) {
            int u = __ldg(&g_src[j]);
            float w = __ldg(&g_w[j]);
            const float4* rp = reinterpret_cast<const float4*>(T + (size_t)u * 256);
            float4 v1 = __ldg(rp + lane);
            float4 v2 = __ldg(rp + 32 + lane);
            a1.x = fmaf(w, v1.x, a1.x); a1.y = fmaf(w, v1.y, a1.y);
            a1.z = fmaf(w, v1.z, a1.z); a1.w = fmaf(w, v1.w, a1.w);
            a2.x = fmaf(w, v2.x, a2.x); a2.y = fmaf(w, v2.y, a2.y);
            a2.z = fmaf(w, v2.z, a2.z); a2.w = fmaf(w, v2.w, a2.w);
        }
        reinterpret_cast<float4*>(out1 + (size_t)node * ld1)[lane] = a1;
        reinterpret_cast<float4*>(out2 + (size_t)node * ld2)[lane] = a2;
        if (do_stats) {
            ls[0] += a1.x; lq[0] = fmaf(a1.x, a1.x, lq[0]);
            ls[1] += a1.y; lq[1] = fmaf(a1.y, a1.y, lq[1]);
            ls[2] += a1.z; lq[2] = fmaf(a1.z, a1.z, lq[2]);
            ls[3] += a1.w; lq[3] = fmaf(a1.w, a1.w, lq[3]);
        }
    }
    if (do_stats) {
        int c = lane * 4;
#pragma unroll
        for (int k = 0; k < 4; k++) {
            atomicAdd(&ssum[c + k], ls[k]);
            atomicAdd(&ssq[c + k], lq[k]);
        }
        __syncthreads();
        if (tid < 128) {
            atomicAdd(&g_sums[128 + tid], (double)ssum[tid]);
            atomicAdd(&g_sums[512 + tid], (double)ssq[tid]);
        }
    }
}

// stage-2 SPMM: Q [NN,128] -> out (h cols 256:384, ld 384), with stats
__global__ void __launch_bounds__(256) k_spmm2(
    const float* __restrict__ Q, float* __restrict__ out, int do_stats)
{
    __shared__ float ssum[128], ssq[128];
    const int tid = threadIdx.x;
    if (tid < 128) { ssum[tid] = 0.f; ssq[tid] = 0.f; }
    __syncthreads();
    const int lane = tid & 31, wp = tid >> 5;
    const int base = blockIdx.x * 64 + wp * 8;
    float ls[4] = {0.f, 0.f, 0.f, 0.f};
    float lq[4] = {0.f, 0.f, 0.f, 0.f};
    for (int nn = 0; nn < 8; nn++) {
        int node = base + nn;
        if (node >= NN) break;
        int s = g_ptr[node], e = g_ptr[node + 1];
        float4 acc = make_float4(0.f, 0.f, 0.f, 0.f);
        for (int j = s; j < e; j++) {
            int u = __ldg(&g_src[j]);
            float w = __ldg(&g_w[j]);
            float4 v = __ldg(reinterpret_cast<const float4*>(Q + (size_t)u * 128) + lane);
            acc.x = fmaf(w, v.x, acc.x);
            acc.y = fmaf(w, v.y, acc.y);
            acc.z = fmaf(w, v.z, acc.z);
            acc.w = fmaf(w, v.w, acc.w);
        }
        reinterpret_cast<float4*>(out + (size_t)node * 384)[lane] = acc;
        if (do_stats) {
            ls[0] += acc.x; lq[0] = fmaf(acc.x, acc.x, lq[0]);
            ls[1] += acc.y; lq[1] = fmaf(acc.y, acc.y, lq[1]);
            ls[2] += acc.z; lq[2] = fmaf(acc.z, acc.z, lq[2]);
            ls[3] += acc.w; lq[3] = fmaf(acc.w, acc.w, lq[3]);
        }
    }
    if (do_stats) {
        int c = lane * 4;
#pragma unroll
        for (int k = 0; k < 4; k++) {
            atomicAdd(&ssum[c + k], ls[k]);
            atomicAdd(&ssq[c + k], lq[k]);
        }
        __syncthreads();
        if (tid < 128) {
            atomicAdd(&g_sums[256 + tid], (double)ssum[tid]);
            atomicAdd(&g_sums[640 + tid], (double)ssq[tid]);
        }
    }
}

// ---------------- TF32 tensor-core GEMM, 3 hops in one launch ----------------
__device__ __forceinline__ uint32_t f2tf32(float x) {
    uint32_t r;
    asm("cvt.rna.tf32.f32 %0, %1;" : "=r"(r) : "f"(x));
    return r;
}
__device__ __forceinline__ void mma_tf32(float* d, const uint32_t* a, const uint32_t* b) {
    asm volatile(
        "mma.sync.aligned.m16n8k8.row.col.f32.tf32.tf32.f32 "
        "{%0,%1,%2,%3}, {%4,%5,%6,%7}, {%8,%9}, {%0,%1,%2,%3};\n"
        : "+f"(d[0]), "+f"(d[1]), "+f"(d[2]), "+f"(d[3])
        : "r"(a[0]), "r"(a[1]), "r"(a[2]), "r"(a[3]),
          "r"(b[0]), "r"(b[1]));
}

#define APITCH 20
#define BPITCH 136

__device__ __forceinline__ void gemm_ldg(
    const float* __restrict__ A, int lda, int M, int row0,
    const float* __restrict__ W, int kt, int tid,
    const float* __restrict__ bnsc, const float* __restrict__ bnsh,
    float4* regA, float4* regB)
{
    const int kb = kt * 16;
    const int c4 = (tid & 3) * 4;
    float4 scv = make_float4(1.f, 1.f, 1.f, 1.f);
    float4 shv = make_float4(0.f, 0.f, 0.f, 0.f);
    if (bnsc) {
        scv = *reinterpret_cast<const float4*>(bnsc + kb + c4);
        shv = *reinterpret_cast<const float4*>(bnsh + kb + c4);
    }
#pragma unroll
    for (int j = 0; j < 4; j++) {
        int m = (tid >> 2) + j * 32;
        float4 v = make_float4(0.f, 0.f, 0.f, 0.f);
        if (row0 + m < M)
            v = *reinterpret_cast<const float4*>(A + (size_t)(row0 + m) * lda + kb + c4);
        if (bnsc) {
            v.x = fmaxf(fmaf(v.x, scv.x, shv.x), 0.f);
            v.y = fmaxf(fmaf(v.y, scv.y, shv.y), 0.f);
            v.z = fmaxf(fmaf(v.z, scv.z, shv.z), 0.f);
            v.w = fmaxf(fmaf(v.w, scv.w, shv.w), 0.f);
        }
        regA[j] = v;
        int kl = (tid >> 5) + j * 4;
        int n4 = (tid & 31) * 4;
        regB[j] = *reinterpret_cast<const float4*>(W + (size_t)(kb + kl) * 128 + n4);
    }
}

__device__ __forceinline__ void gemm_sts(
    uint32_t* __restrict__ As, uint32_t* __restrict__ Bs, int tid,
    const float4* regA, const float4* regB)
{
#pragma unroll
    for (int j = 0; j < 4; j++) {
        int m = (tid >> 2) + j * 32;
        int c4 = (tid & 3) * 4;
        uint32_t* p = As + m * APITCH + c4;
        p[0] = f2tf32(regA[j].x);
        p[1] = f2tf32(regA[j].y);
        p[2] = f2tf32(regA[j].z);
        p[3] = f2tf32(regA[j].w);
        int kl = (tid >> 5) + j * 4;
        int n4 = (tid & 31) * 4;
        uint32_t* q = Bs + kl * BPITCH + n4;
        q[0] = f2tf32(regB[j].x);
        q[1] = f2tf32(regB[j].y);
        q[2] = f2tf32(regB[j].z);
        q[3] = f2tf32(regB[j].w);
    }
}

// gridDim = (ceil(M/128), 3). y selects hop: 0 -> Hout cols 0:128 (stats),
// 1 -> T cols 0:128, 2 -> T cols 128:256.
__global__ void __launch_bounds__(128, 2) k_gemm3(
    const float* __restrict__ A, int lda, int M, int K,
    const float* __restrict__ Wall, const float* __restrict__ ball,
    const float* __restrict__ bnsc, const float* __restrict__ bnsh,
    float* __restrict__ Hout, float* __restrict__ T, int do_stats)
{
    __shared__ uint32_t As[2][128 * APITCH];
    __shared__ uint32_t Bs[2][16 * BPITCH];
    __shared__ float ssum[128], ssq[128];

    const int tid = threadIdx.x;
    const int hop = blockIdx.y;
    const float* W = Wall + (size_t)hop * K * 128;
    const float* bias = ball + hop * 128;
    float* C;
    int ldc;
    if (hop == 0) { C = Hout; ldc = 384; }
    else if (hop == 1) { C = T; ldc = 256; }
    else { C = T + 128; ldc = 256; }
    const int stats = do_stats && (hop == 0);

    if (tid < 128) { ssum[tid] = 0.f; ssq[tid] = 0.f; }

    const int wid = tid >> 5, lane = tid & 31;
    const int g = lane >> 2, t = lane & 3;
    const int wm = (wid >> 1) * 64, wn = (wid & 1) * 64;
    const int row0 = blockIdx.x * 128;

    float acc[4][8][4];
#pragma unroll
    for (int im = 0; im < 4; im++)
#pragma unroll
        for (int in = 0; in < 8; in++)
#pragma unroll
            for (int q = 0; q < 4; q++) acc[im][in][q] = 0.f;

    const int NT = K >> 4;
    float4 regA[4], regB[4];

    gemm_ldg(A, lda, M, row0, W, 0, tid, bnsc, bnsh, regA, regB);
    gemm_sts(As[0], Bs[0], tid, regA, regB);
    __syncthreads();

    for (int kt = 0; kt < NT; kt++) {
        const int buf = kt & 1;
        if (kt + 1 < NT) gemm_ldg(A, lda, M, row0, W, kt + 1, tid, bnsc, bnsh, regA, regB);

        const uint32_t* Ab = As[buf];
        const uint32_t* Bb = Bs[buf];
#pragma unroll
        for (int ks = 0; ks < 16; ks += 8) {
            uint32_t af[4][4], bf[8][2];
#pragma unroll
            for (int im = 0; im < 4; im++) {
                int mb = (wm + im * 16 + g) * APITCH + ks + t;
                af[im][0] = Ab[mb];
                af[im][1] = Ab[mb + 8 * APITCH];
                af[im][2] = Ab[mb + 4];
                af[im][3] = Ab[mb + 8 * APITCH + 4];
            }
#pragma unroll
            for (int in = 0; in < 8; in++) {
                int nb = (ks + t) * BPITCH + wn + in * 8 + g;
                bf[in][0] = Bb[nb];
                bf[in][1] = Bb[nb + 4 * BPITCH];
            }
#pragma unroll
            for (int im = 0; im < 4; im++)
#pragma unroll
                for (int in = 0; in < 8; in++)
                    mma_tf32(acc[im][in], af[im], bf[in]);
        }

        if (kt + 1 < NT) {
            gemm_sts(As[buf ^ 1], Bs[buf ^ 1], tid, regA, regB);
            __syncthreads();
        }
    }

    // epilogue: bias + store (+ optional column stats)
#pragma unroll
    for (int im = 0; im < 4; im++) {
        int r0 = row0 + wm + im * 16 + g;
#pragma unroll
        for (int in = 0; in < 8; in++) {
            int c0 = wn + in * 8 + 2 * t;
            float b0 = __ldg(&bias[c0]), b1 = __ldg(&bias[c0 + 1]);
            if (r0 < M) {
                float2 v = make_float2(acc[im][in][0] + b0, acc[im][in][1] + b1);
                *reinterpret_cast<float2*>(C + (size_t)r0 * ldc + c0) = v;
            }
            if (r0 + 8 < M) {
                float2 v = make_float2(acc[im][in][2] + b0, acc[im][in][3] + b1);
                *reinterpret_cast<float2*>(C + (size_t)(r0 + 8) * ldc + c0) = v;
            }
        }
    }

    if (stats) {
        __syncthreads();  // ssum/ssq zero-init visible
#pragma unroll
        for (int in = 0; in < 8; in++) {
            int c0 = wn + in * 8 + 2 * t;
            float b0 = __ldg(&bias[c0]), b1 = __ldg(&bias[c0 + 1]);
            float s0 = 0.f, s1 = 0.f, q0 = 0.f, q1 = 0.f;
#pragma unroll
            for (int im = 0; im < 4; im++) {
                int r0 = row0 + wm + im * 16 + g;
                if (r0 < M) {
                    float v0 = acc[im][in][0] + b0, v1 = acc[im][in][1] + b1;
                    s0 += v0; q0 = fmaf(v0, v0, q0);
                    s1 += v1; q1 = fmaf(v1, v1, q1);
                }
                if (r0 + 8 < M) {
                    float v0 = acc[im][in][2] + b0, v1 = acc[im][in][3] + b1;
                    s0 += v0; q0 = fmaf(v0, v0, q0);
                    s1 += v1; q1 = fmaf(v1, v1, q1);
                }
            }
            atomicAdd(&ssum[c0], s0);
            atomicAdd(&ssq[c0], q0);
            atomicAdd(&ssum[c0 + 1], s1);
            atomicAdd(&ssq[c0 + 1], q1);
        }
        __syncthreads();
        if (tid < 128) {
            atomicAdd(&g_sums[tid], (double)ssum[tid]);
            atomicAdd(&g_sums[384 + tid], (double)ssq[tid]);
        }
    }
}

// ---------------- BN coefficients ----------------
__global__ void k_zero_sums() {
    int i = threadIdx.x;
    if (i < 768) g_sums[i] = 0.0;
}
__global__ void k_bncoef(const float* __restrict__ gamma, const float* __restrict__ beta) {
    int c = threadIdx.x;  // 384
    double inv_n = 1.0 / (double)NN;
    double mu = g_sums[c] * inv_n;
    double var = g_sums[384 + c] * inv_n - mu * mu;
    float inv = rsqrtf(fmaxf((float)var, 0.f) + 1e-5f);
    float gg = gamma[c];
    g_sc[c] = inv * gg;
    g_sh[c] = beta[c] - (float)mu * inv * gg;
}

// ---------------- host orchestration ----------------
static void run_layer(const float* X, int Kin, const float* Wl, const float* bl,
                      const float* bnsc, const float* bnsh,
                      float* Hout, float* T, float* tmpQ, int do_stats) {
    dim3 gg((NN + 127) / 128, 3);
    const int sg = (NN + 63) / 64;
    k_gemm3<<<gg, 128>>>(X, Kin, NN, Kin, Wl, bl, bnsc, bnsh, Hout, T, do_stats);
    k_spmm256<<<sg, 256>>>(T, Hout + 128, 384, tmpQ, 128, do_stats);
    k_spmm2<<<sg, 256>>>(tmpQ, Hout + 256, do_stats);
}

extern "C" void kernel_launch(void* const* d_in, const int* in_sizes, int n_in,
                              void* d_out, int out_size) {
    const float* x  = (const float*)d_in[0];
    const int*   ei = (const int*)d_in[1];
    const float* W0 = (const float*)d_in[2];
    const float* b0 = (const float*)d_in[3];
    const float* W1 = (const float*)d_in[4];
    const float* b1 = (const float*)d_in[5];
    const float* W2 = (const float*)d_in[6];
    const float* b2 = (const float*)d_in[7];
    const float* gm = (const float*)d_in[8];
    const float* bt = (const float*)d_in[9];
    float* out = (float*)d_out;

    float *bufA, *bufB, *T, *tmpQ, *sc, *sh;
    cudaGetSymbolAddress((void**)&bufA, g_bufA);
    cudaGetSymbolAddress((void**)&bufB, g_bufB);
    cudaGetSymbolAddress((void**)&T, g_tmpT);
    cudaGetSymbolAddress((void**)&tmpQ, g_tmpQ);
    cudaGetSymbolAddress((void**)&sc, g_sc);
    cudaGetSymbolAddress((void**)&sh, g_sh);

    const int* row = ei;
    const int* col = ei + NE;

    // graph preprocessing: degree, norm, CSR by destination
    k_zero_setup<<<(NN + 255) / 256, 256>>>();
    k_hist<<<(NE + 255) / 256, 256>>>(col);
    k_dinv<<<(NN + 255) / 256, 256>>>();
    k_scan1<<<(NN + 1023) / 1024, 1024>>>();
    k_scan2<<<1, 128>>>();
    k_scan3<<<(NN + 255) / 256, 256>>>();
    k_fill<<<(NE + 255) / 256, 256>>>(row, col);

    // layer 0 (no BN on input; stats fused into producers)
    k_zero_sums<<<1, 768>>>();
    run_layer(x, 128, W0, b0, nullptr, nullptr, bufA, T, tmpQ, 1);
    k_bncoef<<<1, 384>>>(gm, bt);

    // layer 1 (BN0+ReLU fused into A-load; stats fused into producers)
    k_zero_sums<<<1, 768>>>();
    run_layer(bufA, 384, W1, b1, sc, sh, bufB, T, tmpQ, 1);
    k_bncoef<<<1, 384>>>(gm + 384, bt + 384);

    // layer 2 (BN1+ReLU fused into A-load) -> output, no stats
    run_layer(bufB, 384, W2, b2, sc, sh, out, T, tmpQ, 0);
}